// round 4
// baseline (speedup 1.0000x reference)
#include <cuda_runtime.h>
#include <cuda_fp16.h>
#include <cstdint>

// MonarchLayer: y[b, l*64+j] = sum_k L[j,k,l] * t1[b,k,j] + bias,
//               t1[b,k,j]    = sum_i x[b,k*64+i] * R[k,i,j]
// Two-stage HMMA (m16n8k16 fp16/fp32) with fp16 global intermediate.
// Inputs (metadata order): x, L, R, bias. Output f32.

#define BATCH 16384
#define DIMN  4096

// ---------------- device scratch (static, allocation-free) ----------------
__device__ __align__(16) __half g_T1[(size_t)BATCH * DIMN];  // 128 MB fp16 intermediate
__device__ __align__(16) __half g_Rh[64 * 64 * 64];          // R fp16 [k][i][j]
__device__ __align__(16) __half g_Lh[64 * 64 * 64];          // L fp16 [j][k][l]

// ---------------- helpers ----------------
__device__ __forceinline__ uint32_t smem_u32(const void* p) {
    uint32_t a;
    asm("{ .reg .u64 t; cvta.to.shared.u64 t, %1; cvt.u32.u64 %0, t; }" : "=r"(a) : "l"(p));
    return a;
}
// XOR swizzle for 128B-row tiles, 16B granularity.
__device__ __forceinline__ int swz(int row, int chunk) {
    return row * 128 + (((chunk) ^ (row & 7)) << 4);
}
__device__ __forceinline__ void ldm_x4(uint32_t* r, uint32_t addr) {
    asm volatile("ldmatrix.sync.aligned.m8n8.x4.shared.b16 {%0,%1,%2,%3}, [%4];"
                 : "=r"(r[0]), "=r"(r[1]), "=r"(r[2]), "=r"(r[3]) : "r"(addr));
}
__device__ __forceinline__ void ldm_x2t(uint32_t* r, uint32_t addr) {
    asm volatile("ldmatrix.sync.aligned.m8n8.x2.trans.shared.b16 {%0,%1}, [%2];"
                 : "=r"(r[0]), "=r"(r[1]) : "r"(addr));
}
__device__ __forceinline__ void mma16816(float* c, const uint32_t* a, const uint32_t* b) {
    asm volatile("mma.sync.aligned.m16n8k16.row.col.f32.f16.f16.f32 "
                 "{%0,%1,%2,%3}, {%4,%5,%6,%7}, {%8,%9}, {%0,%1,%2,%3};"
                 : "+f"(c[0]), "+f"(c[1]), "+f"(c[2]), "+f"(c[3])
                 : "r"(a[0]), "r"(a[1]), "r"(a[2]), "r"(a[3]), "r"(b[0]), "r"(b[1]));
}

// ---------------- prep: cast L,R to fp16 ----------------
__global__ void monarch_prep(const float* __restrict__ L, const float* __restrict__ R) {
    int idx = blockIdx.x * blockDim.x + threadIdx.x;
    if (idx < 64 * 64 * 64) {
        g_Rh[idx] = __float2half_rn(R[idx]);
        g_Lh[idx] = __float2half_rn(L[idx]);
    }
}

// ---------------- stage 1: T1[b, k*64+j] = sum_i x[b,k*64+i] * R[k,i,j] ----------------
// grid: (64 k-blocks, 128 batch tiles), 256 threads, batch tile = 128 rows.
__global__ __launch_bounds__(256) void monarch_k1(const float* __restrict__ x) {
    __shared__ __align__(16) unsigned char sA[128 * 128];
    __shared__ __align__(16) unsigned char sB[64 * 128];

    const int kblk = blockIdx.x;
    const size_t b0 = (size_t)blockIdx.y * 128;
    const int tid = threadIdx.x;

#pragma unroll
    for (int i = 0; i < 4; i++) {
        int cid = tid + i * 256;
        int r = cid >> 3, c = cid & 7;
        const float4* gp = (const float4*)(x + (b0 + r) * DIMN + kblk * 64 + c * 8);
        float4 f0 = gp[0], f1 = gp[1];
        uint4 pk;
        __half2* hp = (__half2*)&pk;
        hp[0] = __floats2half2_rn(f0.x, f0.y);
        hp[1] = __floats2half2_rn(f0.z, f0.w);
        hp[2] = __floats2half2_rn(f1.x, f1.y);
        hp[3] = __floats2half2_rn(f1.z, f1.w);
        *(uint4*)(sA + swz(r, c)) = pk;
    }
#pragma unroll
    for (int i = 0; i < 2; i++) {
        int cid = tid + i * 256;
        int r = cid >> 3, c = cid & 7;
        uint4 v = *(const uint4*)(g_Rh + kblk * 4096 + r * 64 + c * 8);
        *(uint4*)(sB + swz(r, c)) = v;
    }
    __syncthreads();

    const int w = tid >> 5, lane = tid & 31;
    const int rbase = w << 4;
    const uint32_t sa = smem_u32(sA), sb = smem_u32(sB);

    float acc[8][4];
#pragma unroll
    for (int nt = 0; nt < 8; nt++)
#pragma unroll
        for (int c = 0; c < 4; c++) acc[nt][c] = 0.f;

#pragma unroll
    for (int kk = 0; kk < 4; kk++) {
        uint32_t a[4];
        {
            int row = rbase + ((lane >> 3) & 1) * 8 + (lane & 7);
            int ch = 2 * kk + (lane >> 4);
            ldm_x4(a, sa + swz(row, ch));
        }
#pragma unroll
        for (int nt = 0; nt < 8; nt++) {
            uint32_t bf[2];
            int row = kk * 16 + (lane & 15);
            ldm_x2t(bf, sb + swz(row, nt));
            mma16816(acc[nt], a, bf);
        }
    }
    __syncthreads();

    const int gr = lane >> 2, q = lane & 3;
#pragma unroll
    for (int nt = 0; nt < 8; nt++) {
        int r0 = rbase + gr, r1 = r0 + 8;
        *(__half2*)(sA + swz(r0, nt) + q * 4) = __floats2half2_rn(acc[nt][0], acc[nt][1]);
        *(__half2*)(sA + swz(r1, nt) + q * 4) = __floats2half2_rn(acc[nt][2], acc[nt][3]);
    }
    __syncthreads();

#pragma unroll
    for (int i = 0; i < 4; i++) {
        int cid = tid + i * 256;
        int r = cid >> 3, c = cid & 7;
        uint4 v = *(uint4*)(sA + swz(r, c));
        *(uint4*)(g_T1 + (b0 + r) * DIMN + kblk * 64 + c * 8) = v;
    }
}

// ---------------- stage 2: y[b, l*64+j] = sum_k T1[b,k*64+j] * L[j,k,l] + bias ----------------
// CTA: 64 batch rows x 16 j, 512 threads. grid (4 j-groups, 256 row tiles).
// smem: sA 16 planes x 8KB = 128KB (T1 transposed, [jplane][row][k] swizzled)
//       sL 16 j x (64k x 8l) = 16KB   (streamed per l-chunk)
//       sO 64 rows x 8l x 16j f32 = 32KB (output staging, row-XOR swizzled)
#define K2_SMEM (131072 + 16384 + 32768)

__global__ __launch_bounds__(512) void monarch_k2(float* __restrict__ out,
                                                  const float* __restrict__ bias) {
    extern __shared__ unsigned char smem[];
    unsigned char* sA = smem;
    unsigned char* sL = smem + 131072;
    unsigned char* sO = smem + 147456;

    const int jg = blockIdx.x;             // j-group: j in [jg*16, jg*16+16)
    const size_t b0 = (size_t)blockIdx.y * 64;
    const int tid = threadIdx.x;
    const int w = tid >> 5, lane = tid & 31;
    const int rs = w & 3, jw = w >> 2;     // row strip (16 rows), j quad (4 j)

    // ---- fill A planes: transpose-gather T1 into 16 j-planes of [64 rows x 64 k]
    // Full-sector (32B) reads; conflict-free half2 scatter (row warp-uniform, k=2*lane).
#pragma unroll
    for (int i = 0; i < 4; i++) {
        int idx = tid + i * 512;           // 0..2047
        int r = idx >> 5, kp = idx & 31;
        int k = kp * 2;
        const __half* gp = g_T1 + (b0 + r) * DIMN + (size_t)k * 64 + jg * 16;
        uint4 v0 = *(const uint4*)gp;          // col k,  j 0..7
        uint4 v0b = *(const uint4*)(gp + 8);   // col k,  j 8..15
        uint4 v1 = *(const uint4*)(gp + 64);   // col k+1, j 0..7
        uint4 v1b = *(const uint4*)(gp + 72);  // col k+1, j 8..15
        const __half* h0 = (const __half*)&v0;
        const __half* h0b = (const __half*)&v0b;
        const __half* h1 = (const __half*)&v1;
        const __half* h1b = (const __half*)&v1b;
        int base = swz(r, k >> 3) + (k & 7) * 2;
#pragma unroll
        for (int s = 0; s < 8; s++)
            *(__half2*)(sA + s * 8192 + base) = __halves2half2(h0[s], h1[s]);
#pragma unroll
        for (int s = 0; s < 8; s++)
            *(__half2*)(sA + (s + 8) * 8192 + base) = __halves2half2(h0b[s], h1b[s]);
    }
    __syncthreads();

    // ---- hoist A fragments for this warp's 4 j planes (reused across all 8 l-chunks)
    const uint32_t sa32 = smem_u32(sA);
    const uint32_t sl32 = smem_u32(sL);
    const int arow = rs * 16 + ((lane >> 3) & 1) * 8 + (lane & 7);
    uint32_t afr[4][4][4];  // [jl][kstep][frag]
#pragma unroll
    for (int jl = 0; jl < 4; jl++) {
        int jj = jw * 4 + jl;
#pragma unroll
        for (int kk = 0; kk < 4; kk++) {
            int ch = 2 * kk + (lane >> 4);
            ldm_x4(afr[jl][kk], sa32 + jj * 8192 + swz(arow, ch));
        }
    }

    const int cr0 = rs * 16 + (lane >> 2);
    const int lq = (lane & 3) * 2;
    const int fl = lane >> 4;      // flush: l offset (0/1)
    const int fj = lane & 15;      // flush: j local

    for (int lc = 0; lc < 8; lc++) {
        // load L sub-tile for this l-chunk: [16 j][64 k][8 l] fp16 (16B rows)
#pragma unroll
        for (int i = 0; i < 2; i++) {
            int idx = tid + i * 512;       // 0..1023
            int jj = idx >> 6, k = idx & 63;
            uint4 v = *(const uint4*)(g_Lh + (size_t)(jg * 16 + jj) * 4096 + k * 64 + lc * 8);
            *(uint4*)(sL + jj * 1024 + k * 16) = v;
        }
        // flush previous l-chunk (overlaps with L load)
        if (lc > 0) {
            int lcp = lc - 1;
#pragma unroll
            for (int t = 0; t < 16; t++) {
                int unit = w * 16 + t;
                int row = unit >> 2;
                int l = (unit & 3) * 2 + fl;
                float v = *(float*)(sO + row * 512 + ((l * 64 + fj * 4) ^ ((row & 7) << 2)));
                int col = (lcp * 8 + l) * 64 + jg * 16 + fj;
                out[(b0 + row) * DIMN + col] = v + __ldg(bias + col);
            }
        }
        __syncthreads();

        // compute: per warp 4 j x (4 B-ldmatrix + 4 MMA), stage C frags to sO
#pragma unroll
        for (int jl = 0; jl < 4; jl++) {
            int jj = jw * 4 + jl;
            uint32_t pb = sl32 + jj * 1024;
            float acc[4] = {0.f, 0.f, 0.f, 0.f};
#pragma unroll
            for (int kk = 0; kk < 4; kk++) {
                uint32_t bf[2];
                ldm_x2t(bf, pb + (kk * 16 + (lane & 15)) * 16);
                mma16816(acc, afr[jl][kk], bf);
            }
            int r1 = cr0 + 8;
            *(float*)(sO + cr0 * 512 + ((lq * 64 + jj * 4) ^ ((cr0 & 7) << 2))) = acc[0];
            *(float*)(sO + cr0 * 512 + (((lq + 1) * 64 + jj * 4) ^ ((cr0 & 7) << 2))) = acc[1];
            *(float*)(sO + r1 * 512 + ((lq * 64 + jj * 4) ^ ((r1 & 7) << 2))) = acc[2];
            *(float*)(sO + r1 * 512 + (((lq + 1) * 64 + jj * 4) ^ ((r1 & 7) << 2))) = acc[3];
        }
        __syncthreads();
    }
    // final flush (lc = 7)
#pragma unroll
    for (int t = 0; t < 16; t++) {
        int unit = w * 16 + t;
        int row = unit >> 2;
        int l = (unit & 3) * 2 + fl;
        float v = *(float*)(sO + row * 512 + ((l * 64 + fj * 4) ^ ((row & 7) << 2)));
        int col = (7 * 8 + l) * 64 + jg * 16 + fj;
        out[(b0 + row) * DIMN + col] = v + __ldg(bias + col);
    }
}

// ---------------- launch ----------------
extern "C" void kernel_launch(void* const* d_in, const int* in_sizes, int n_in,
                              void* d_out, int out_size) {
    (void)in_sizes; (void)n_in; (void)out_size;
    const float* x    = (const float*)d_in[0];
    const float* L    = (const float*)d_in[1];
    const float* R    = (const float*)d_in[2];
    const float* bias = (const float*)d_in[3];
    float* out = (float*)d_out;

    cudaFuncSetAttribute(monarch_k2, cudaFuncAttributeMaxDynamicSharedMemorySize, K2_SMEM);

    monarch_prep<<<1024, 256>>>(L, R);
    monarch_k1<<<dim3(64, 128), 256>>>(x);
    monarch_k2<<<dim3(4, 256), 512, K2_SMEM>>>(out, bias);
}